// round 14
// baseline (speedup 1.0000x reference)
#include <cuda_runtime.h>
#include <math.h>

#define Dm     256
#define Kc     128
#define NTOK   131072
#define TM     256
#define DC     32
#define NTILES (NTOK / TM)        // 512
#define NTHR   256
#define MAXCTA 256

// output layout (float32, tuple order flattened+concatenated)
#define OFF_Q    ((size_t)1)
#define OFF_PERP ((size_t)1 + (size_t)NTOK * Dm)
#define OFF_ENC  (OFF_PERP + 1)
#define OFF_IDX  (OFF_ENC + (size_t)NTOK * Kc)

__device__ int   g_hist[MAXCTA * Kc];
__device__ float g_partials[MAXCTA];
__device__ int   g_done = 0;

union F2 { float2 f; unsigned long long u; };

__device__ __forceinline__ void fma2(unsigned long long& c, unsigned long long a, unsigned long long b) {
    asm("fma.rn.f32x2 %0, %1, %2, %0;" : "+l"(c) : "l"(a), "l"(b));
}

// smem floats: As 2*32*256=16384 (64KB), Bs 256*128=32768 (128KB),
//              e2s 128, red 256, sidx int 256, chist int 128, tick int 4
#define SMEM_FLOATS (16384 + 32768 + 128 + 256 + 256 + 128 + 4)
#define SMEM_BYTES  (SMEM_FLOATS * 4)    // 199,696 B

extern __shared__ float smem[];

__global__ void __launch_bounds__(NTHR, 1) vq_kernel(
    const float* __restrict__ inp,
    const float* __restrict__ emb,
    float* __restrict__ out,
    int ncta)
{
    float* As    = smem;                     // [2][32][256] swizzled
    float* Bs    = smem + 16384;             // [256][128]
    float* e2s   = Bs + Dm * Kc;             // [128]
    float* red   = e2s + Kc;                 // [256]
    int*   sidx  = (int*)(red + NTHR);       // [256]
    int*   chist = sidx + TM;                // [128]
    int*   tick  = chist + Kc;

    const int tid = threadIdx.x;
    const int tx  = tid & 7;     // code octet: codes q4*32 + tx*4 + j
    const int ty  = tid >> 3;    // token group: tokens ty*8 .. ty*8+7  (0..31)
    const int cta = blockIdx.x;

    if (tid < Kc) chist[tid] = 0;

    // ---- stage B: Bs[d][code] natural layout; exact fp32 ||e||^2 ----
    {
        int code = tid >> 1, half = tid & 1;
        const float* src = emb + code * Dm + half * 128;
        float es = 0.f;
        #pragma unroll 8
        for (int i = 0; i < 32; i++) {
            float4 v = *(const float4*)(src + i * 4);
            es = fmaf(v.x, v.x, es); es = fmaf(v.y, v.y, es);
            es = fmaf(v.z, v.z, es); es = fmaf(v.w, v.w, es);
            int d = half * 128 + i * 4;
            Bs[(d + 0) * Kc + code] = v.x;
            Bs[(d + 1) * Kc + code] = v.y;
            Bs[(d + 2) * Kc + code] = v.z;
            Bs[(d + 3) * Kc + code] = v.w;
        }
        es += __shfl_xor_sync(0xffffffffu, es, 1);
        if (half == 0) e2s[code] = es;
    }
    __syncthreads();

    float lsum = 0.f;

    // ================= persistent tile loop =================
    for (int tile = cta; tile < NTILES; tile += ncta) {
        const int tb = tile * TM;
        float4 r[8];

        // ---- stage chunk 0: coalesced LDG, swizzled conflict-free STS, +x^2 ----
        // thread (sf=tx, st=ty): tokens st+32q, d_local = sf*4..+3
        #pragma unroll
        for (int q = 0; q < 8; q++)
            r[q] = *(const float4*)(inp + (size_t)(tb + ty + 32 * q) * Dm + tx * 4);
        {
            float* A0 = As;
            #pragma unroll
            for (int q = 0; q < 8; q++) {
                int tok = ty + 32 * q;
                int g = (tok >> 2) ^ tx;                 // swizzle key = d_local>>2 = sf = tx
                float* p = A0 + (tx * 4) * 256 + 4 * g + (tok & 3);
                p[0]   = r[q].x;
                p[256] = r[q].y;
                p[512] = r[q].z;
                p[768] = r[q].w;
                float s = r[q].x * r[q].x;
                s = fmaf(r[q].y, r[q].y, s);
                s = fmaf(r[q].z, r[q].z, s);
                lsum += fmaf(r[q].w, r[q].w, s);          // Sum x^2 (each elem once)
            }
        }
        __syncthreads();

        // ---- accumulators: 4 token-pairs x 16 codes ----
        unsigned long long acc[4][16];
        #pragma unroll
        for (int p = 0; p < 4; p++)
            #pragma unroll
            for (int cc = 0; cc < 16; cc++) acc[p][cc] = 0ull;

        #pragma unroll 1
        for (int c = 0; c < Dm / DC; c++) {
            if (c < Dm / DC - 1) {
                #pragma unroll
                for (int q = 0; q < 8; q++)
                    r[q] = *(const float4*)(inp + (size_t)(tb + ty + 32 * q) * Dm
                                            + (c + 1) * DC + tx * 4);
            }
            const float* Ac = As + (c & 1) * 8192;
            #pragma unroll 8
            for (int k = 0; k < DC; k++) {
                int kk = k >> 2;
                const float* ar = Ac + k * 256;
                float4 a0 = *(const float4*)(ar + 4 * ((2 * ty) ^ kk));
                float4 a1 = *(const float4*)(ar + 4 * ((2 * ty + 1) ^ kk));
                F2 av[4];
                av[0].f = make_float2(a0.x, a0.y);
                av[1].f = make_float2(a0.z, a0.w);
                av[2].f = make_float2(a1.x, a1.y);
                av[3].f = make_float2(a1.z, a1.w);
                const float* Bk = Bs + (c * DC + k) * Kc + tx * 4;
                #pragma unroll
                for (int q4 = 0; q4 < 4; q4++) {
                    float4 b = *(const float4*)(Bk + q4 * 32);
                    F2 bd0; bd0.f = make_float2(b.x, b.x);
                    F2 bd1; bd1.f = make_float2(b.y, b.y);
                    F2 bd2; bd2.f = make_float2(b.z, b.z);
                    F2 bd3; bd3.f = make_float2(b.w, b.w);
                    #pragma unroll
                    for (int p = 0; p < 4; p++) {
                        fma2(acc[p][q4 * 4 + 0], av[p].u, bd0.u);
                        fma2(acc[p][q4 * 4 + 1], av[p].u, bd1.u);
                        fma2(acc[p][q4 * 4 + 2], av[p].u, bd2.u);
                        fma2(acc[p][q4 * 4 + 3], av[p].u, bd3.u);
                    }
                }
            }
            if (c < Dm / DC - 1) {
                float* An = As + ((c + 1) & 1) * 8192;
                #pragma unroll
                for (int q = 0; q < 8; q++) {
                    int tok = ty + 32 * q;
                    int g = (tok >> 2) ^ tx;
                    float* p = An + (tx * 4) * 256 + 4 * g + (tok & 3);
                    p[0]   = r[q].x;
                    p[256] = r[q].y;
                    p[512] = r[q].z;
                    p[768] = r[q].w;
                    float s = r[q].x * r[q].x;
                    s = fmaf(r[q].y, r[q].y, s);
                    s = fmaf(r[q].z, r[q].z, s);
                    lsum += fmaf(r[q].w, r[q].w, s);
                }
            }
            __syncthreads();
        }

        // ---- argmin per token: score = ||e||^2 - 2 dot; loss += best ----
        float bsum = 0.f;
        #pragma unroll
        for (int t = 0; t < 8; t++) {
            int p = t >> 1, h = t & 1;
            float best = 3.402823466e38f;
            int   bi   = 0;
            #pragma unroll
            for (int cc = 0; cc < 16; cc++) {
                F2 a; a.u = acc[p][cc];
                float dot = h ? a.f.y : a.f.x;
                int code = (cc >> 2) * 32 + tx * 4 + (cc & 3);   // ascending in cc
                float s = fmaf(-2.0f, dot, e2s[code]);
                if (s < best) { best = s; bi = code; }
            }
            #pragma unroll
            for (int m = 1; m < 8; m <<= 1) {
                float ov = __shfl_xor_sync(0xffffffffu, best, m);
                int   oi = __shfl_xor_sync(0xffffffffu, bi,   m);
                if (ov < best || (ov == best && oi < bi)) { best = ov; bi = oi; }
            }
            if (tx == 0) { sidx[ty * 8 + t] = bi; bsum += best; }
        }
        if (tx == 0) lsum += bsum;
        __syncthreads();   // sidx ready

        // histogram (one thread per token; TM == NTHR)
        atomicAdd(&chist[sidx[tid]], 1);

        // ---- quantized output (region starts at elem 1 -> scalar stores) ----
        float* out_q = out + OFF_Q;
        #pragma unroll 1
        for (int i = tid; i < TM * (Dm / 4); i += NTHR) {   // 64 iters
            int tok = i >> 6, f4 = i & 63;
            int k2 = sidx[tok];
            float4 e = *(const float4*)(emb + (size_t)k2 * Dm + f4 * 4);
            float* qp = out_q + (size_t)(tb + tok) * Dm + f4 * 4;
            qp[0] = e.x; qp[1] = e.y; qp[2] = e.z; qp[3] = e.w;
        }

        // ---- one-hot encodings (region start == 2 mod 4 -> float2 ok) ----
        float* out_e = out + OFF_ENC;
        #pragma unroll 1
        for (int i = tid; i < TM * (Kc / 4); i += NTHR) {   // 32 iters
            int tok = i >> 5, f4 = i & 31;
            int k2 = sidx[tok];
            int d0 = f4 * 4;
            float2 v01, v23;
            v01.x = (d0 + 0 == k2) ? 1.f : 0.f;
            v01.y = (d0 + 1 == k2) ? 1.f : 0.f;
            v23.x = (d0 + 2 == k2) ? 1.f : 0.f;
            v23.y = (d0 + 3 == k2) ? 1.f : 0.f;
            float* ep = out_e + (size_t)(tb + tok) * Kc + d0;
            *(float2*)(ep)     = v01;
            *(float2*)(ep + 2) = v23;
        }

        // indices (as float)
        out[OFF_IDX + tb + tid] = (float)sidx[tid];
        __syncthreads();   // protect sidx before next tile's argmin
    }

    // ================= per-CTA results =================
    red[tid] = lsum;
    __syncthreads();
    #pragma unroll
    for (int s = NTHR / 2; s > 0; s >>= 1) {
        if (tid < s) red[tid] += red[tid + s];
        __syncthreads();
    }
    if (tid == 0) g_partials[cta] = red[0];
    if (tid < Kc) g_hist[cta * Kc + tid] = chist[tid];

    __syncthreads();
    __threadfence();
    if (tid == 0) tick[0] = atomicAdd(&g_done, 1);
    __syncthreads();

    // ================= last CTA: loss + perplexity =================
    if (tick[0] == ncta - 1) {
        __threadfence();
        float term = 0.f;
        if (tid < Kc) {
            int cnt = 0;
            for (int b = 0; b < ncta; b++) cnt += g_hist[b * Kc + tid];
            float p = (float)cnt / (float)NTOK;
            term = p * logf(p + 1e-10f);
        }
        red[tid] = term;
        __syncthreads();
        #pragma unroll
        for (int s = NTHR / 2; s > 0; s >>= 1) {
            if (tid < s) red[tid] += red[tid + s];
            __syncthreads();
        }
        float perp = expf(-red[0]);
        __syncthreads();

        red[tid] = (tid < ncta) ? g_partials[tid] : 0.f;
        __syncthreads();
        #pragma unroll
        for (int s = NTHR / 2; s > 0; s >>= 1) {
            if (tid < s) red[tid] += red[tid + s];
            __syncthreads();
        }
        if (tid == 0) {
            out[0]        = 0.25f * red[0] / ((float)NTOK * (float)Dm);
            out[OFF_PERP] = perp;
            g_done = 0;                     // reset for next graph replay
        }
    }
}

// ---------------- launch ----------------
extern "C" void kernel_launch(void* const* d_in, const int* in_sizes, int n_in,
                              void* d_out, int out_size) {
    const float* inp = (const float*)d_in[0];   // [64,2048,256] f32
    const float* emb = (const float*)d_in[1];   // [128,256]     f32
    float* out = (float*)d_out;

    int nsm = 0;
    cudaDeviceGetAttribute(&nsm, cudaDevAttrMultiProcessorCount, 0);
    if (nsm <= 0) nsm = 148;
    if (nsm > MAXCTA) nsm = MAXCTA;
    if (nsm > NTILES) nsm = NTILES;

    cudaFuncSetAttribute(vq_kernel,
                         cudaFuncAttributeMaxDynamicSharedMemorySize, SMEM_BYTES);

    vq_kernel<<<nsm, NTHR, SMEM_BYTES>>>(inp, emb, out, nsm);
}

// round 15
// speedup vs baseline: 1.4065x; 1.4065x over previous
#include <cuda_runtime.h>
#include <math.h>

#define Dm     256
#define Kc     128
#define NTOK   131072
#define TM     256
#define DC     32
#define NTILES (NTOK / TM)        // 512
#define NTHR   512
#define MAXCTA 256

// output layout (float32, tuple order flattened+concatenated)
#define OFF_Q    ((size_t)1)
#define OFF_PERP ((size_t)1 + (size_t)NTOK * Dm)
#define OFF_ENC  (OFF_PERP + 1)
#define OFF_IDX  (OFF_ENC + (size_t)NTOK * Kc)

__device__ int   g_hist[MAXCTA * Kc];
__device__ float g_partials[MAXCTA];
__device__ int   g_done = 0;

union F2 { float2 f; unsigned long long u; };

__device__ __forceinline__ void fma2(unsigned long long& c, unsigned long long a, unsigned long long b) {
    asm("fma.rn.f32x2 %0, %1, %2, %0;" : "+l"(c) : "l"(a), "l"(b));
}

// smem floats: As 2*32*256=16384 (64KB), Bs 256*128=32768 (128KB swizzled),
//              e2s 128, red 512, sidx int 256, chist int 128, tick int 4
#define SMEM_FLOATS (16384 + 32768 + 128 + 512 + 256 + 128 + 4)
#define SMEM_BYTES  (SMEM_FLOATS * 4)    // ~200.7 KB

extern __shared__ float smem[];

__global__ void __launch_bounds__(NTHR, 1) vq_kernel(
    const float* __restrict__ inp,
    const float* __restrict__ emb,
    float* __restrict__ out,
    int ncta)
{
    float* As    = smem;                     // [2][32][256] token-swizzled
    float* Bs    = smem + 16384;             // [256][128] code-swizzled (R5 layout)
    float* e2s   = Bs + Dm * Kc;             // [128]
    float* red   = e2s + Kc;                 // [512]
    int*   sidx  = (int*)(red + NTHR);       // [256]
    int*   chist = sidx + TM;                // [128]
    int*   tick  = chist + Kc;

    const int tid = threadIdx.x;
    const int tx  = tid & 15;    // code group: codes 4tx..4tx+3, 64+4tx..+3
    const int ty  = tid >> 4;    // token group: tokens 8ty..8ty+7  (0..31)
    const int lf4 = tid & 7;     // staging: d-slot (sf key)
    const int lt  = tid >> 3;    // staging: token lane 0..63
    const int cta = blockIdx.x;

    if (tid < Kc) chist[tid] = 0;

    // ---- stage B swizzled: word(d,c) = d*Kc + (((c>>2)^((d>>2)&31))<<2)+(c&3) ----
    for (int i = tid; i < Kc * (Dm / 4); i += NTHR) {   // 16 iters
        int code = i >> 6;
        int f4   = i & 63;
        float4 v = *(const float4*)(emb + code * Dm + f4 * 4);
        int slot = (code >> 2) ^ (f4 & 31);
        float* p = Bs + (f4 * 4) * Kc + (slot << 2) + (code & 3);
        p[0]      = v.x;
        p[Kc]     = v.y;
        p[2 * Kc] = v.z;
        p[3 * Kc] = v.w;
    }
    __syncthreads();

    // ---- ||e_k||^2 from swizzled Bs (4 threads per code) ----
    {
        int code = tid >> 2, part = tid & 3;
        int c2 = code >> 2, cl = code & 3;
        float s = 0.f;
        #pragma unroll 8
        for (int i = 0; i < 64; i++) {
            int d = part * 64 + i;
            int slot = c2 ^ ((d >> 2) & 31);
            float v = Bs[d * Kc + (slot << 2) + cl];
            s = fmaf(v, v, s);
        }
        s += __shfl_xor_sync(0xffffffffu, s, 1);
        s += __shfl_xor_sync(0xffffffffu, s, 2);
        if (part == 0) e2s[code] = s;
    }
    __syncthreads();

    float lsum = 0.f;

    // ================= persistent tile loop =================
    for (int tile = cta; tile < NTILES; tile += ncta) {
        const int tb = tile * TM;
        float4 r[4];

        // ---- stage chunk 0: coalesced LDG + conflict-free swizzled STS + x^2 ----
        #pragma unroll
        for (int q = 0; q < 4; q++)
            r[q] = *(const float4*)(inp + (size_t)(tb + lt + 64 * q) * Dm + lf4 * 4);
        #pragma unroll
        for (int q = 0; q < 4; q++) {
            int tok = lt + 64 * q;
            int g = (tok >> 2) ^ lf4;        // token-group swizzle, key = d>>2 = lf4
            float* p = As + (lf4 * 4) * 256 + 4 * g + (tok & 3);
            p[0]   = r[q].x;
            p[256] = r[q].y;
            p[512] = r[q].z;
            p[768] = r[q].w;
            float s = r[q].x * r[q].x;
            s = fmaf(r[q].y, r[q].y, s);
            s = fmaf(r[q].z, r[q].z, s);
            lsum += fmaf(r[q].w, r[q].w, s);  // Sum x^2 (each element once)
        }
        __syncthreads();

        // ---- accumulators: 4 token-pairs (8 tokens) x 8 codes ----
        unsigned long long acc[4][8];
        #pragma unroll
        for (int p = 0; p < 4; p++)
            #pragma unroll
            for (int cc = 0; cc < 8; cc++) acc[p][cc] = 0ull;

        #pragma unroll 1
        for (int c = 0; c < Dm / DC; c++) {
            if (c < Dm / DC - 1) {
                #pragma unroll
                for (int q = 0; q < 4; q++)
                    r[q] = *(const float4*)(inp + (size_t)(tb + lt + 64 * q) * Dm
                                            + (c + 1) * DC + lf4 * 4);
            }
            const float* Ac = As + (c & 1) * 8192;
            #pragma unroll 8
            for (int k = 0; k < DC; k++) {
                int kk = k >> 2;
                const float* ar = Ac + k * 256;
                float4 a0 = *(const float4*)(ar + 4 * ((2 * ty) ^ kk));
                float4 a1 = *(const float4*)(ar + 4 * ((2 * ty + 1) ^ kk));
                int d  = c * DC + k;
                int sl = (tx ^ ((d >> 2) & 31)) << 2;
                float4 b0 = *(const float4*)(Bs + d * Kc + sl);
                float4 b1 = *(const float4*)(Bs + d * Kc + (sl ^ 64));
                F2 av[4];
                av[0].f = make_float2(a0.x, a0.y);
                av[1].f = make_float2(a0.z, a0.w);
                av[2].f = make_float2(a1.x, a1.y);
                av[3].f = make_float2(a1.z, a1.w);
                float bb[8] = {b0.x, b0.y, b0.z, b0.w, b1.x, b1.y, b1.z, b1.w};
                #pragma unroll
                for (int cc = 0; cc < 8; cc++) {
                    F2 bd; bd.f = make_float2(bb[cc], bb[cc]);
                    #pragma unroll
                    for (int p = 0; p < 4; p++) fma2(acc[p][cc], av[p].u, bd.u);
                }
            }
            if (c < Dm / DC - 1) {
                float* An = As + ((c + 1) & 1) * 8192;
                #pragma unroll
                for (int q = 0; q < 4; q++) {
                    int tok = lt + 64 * q;
                    int g = (tok >> 2) ^ lf4;
                    float* p = An + (lf4 * 4) * 256 + 4 * g + (tok & 3);
                    p[0]   = r[q].x;
                    p[256] = r[q].y;
                    p[512] = r[q].z;
                    p[768] = r[q].w;
                    float s = r[q].x * r[q].x;
                    s = fmaf(r[q].y, r[q].y, s);
                    s = fmaf(r[q].z, r[q].z, s);
                    lsum += fmaf(r[q].w, r[q].w, s);
                }
            }
            __syncthreads();
        }

        // ---- argmin per token: score = ||e||^2 - 2 dot; loss += best ----
        float e2r[8];
        #pragma unroll
        for (int j = 0; j < 4; j++) {
            e2r[j]     = e2s[tx * 4 + j];
            e2r[4 + j] = e2s[64 + tx * 4 + j];
        }
        float bsum = 0.f;
        #pragma unroll
        for (int t = 0; t < 8; t++) {
            float best = 3.402823466e38f;
            int   bi   = 0;
            #pragma unroll
            for (int cc = 0; cc < 8; cc++) {
                F2 a; a.u = acc[t >> 1][cc];
                float dot = (t & 1) ? a.f.y : a.f.x;
                float s = fmaf(-2.0f, dot, e2r[cc]);
                int code = (cc < 4) ? (tx * 4 + cc) : (64 + tx * 4 + (cc - 4));
                if (s < best) { best = s; bi = code; }
            }
            #pragma unroll
            for (int m = 1; m < 16; m <<= 1) {
                float ov = __shfl_xor_sync(0xffffffffu, best, m);
                int   oi = __shfl_xor_sync(0xffffffffu, bi,   m);
                if (ov < best || (ov == best && oi < bi)) { best = ov; bi = oi; }
            }
            if (tx == 0) { sidx[ty * 8 + t] = bi; bsum += best; }
        }
        if (tx == 0) lsum += bsum;
        __syncthreads();   // sidx ready

        // histogram
        if (tid < TM) atomicAdd(&chist[sidx[tid]], 1);

        // ---- quantized output (region starts at elem 1 -> scalar stores) ----
        float* out_q = out + OFF_Q;
        #pragma unroll 1
        for (int i = tid; i < TM * (Dm / 4); i += NTHR) {   // 32 iters
            int tok = i >> 6, f4 = i & 63;
            int k2 = sidx[tok];
            float4 e = *(const float4*)(emb + (size_t)k2 * Dm + f4 * 4);
            float* qp = out_q + (size_t)(tb + tok) * Dm + f4 * 4;
            qp[0] = e.x; qp[1] = e.y; qp[2] = e.z; qp[3] = e.w;
        }

        // ---- one-hot encodings (region start == 2 mod 4 -> float2 ok) ----
        float* out_e = out + OFF_ENC;
        #pragma unroll 1
        for (int i = tid; i < TM * (Kc / 4); i += NTHR) {   // 16 iters
            int tok = i >> 5, f4 = i & 31;
            int k2 = sidx[tok];
            int d0 = f4 * 4;
            float2 v01, v23;
            v01.x = (d0 + 0 == k2) ? 1.f : 0.f;
            v01.y = (d0 + 1 == k2) ? 1.f : 0.f;
            v23.x = (d0 + 2 == k2) ? 1.f : 0.f;
            v23.y = (d0 + 3 == k2) ? 1.f : 0.f;
            float* ep = out_e + (size_t)(tb + tok) * Kc + d0;
            *(float2*)(ep)     = v01;
            *(float2*)(ep + 2) = v23;
        }

        // indices (as float)
        if (tid < TM) out[OFF_IDX + tb + tid] = (float)sidx[tid];
        __syncthreads();   // protect sidx/As before next tile
    }

    // ================= per-CTA results =================
    red[tid] = lsum;
    __syncthreads();
    #pragma unroll
    for (int s = NTHR / 2; s > 0; s >>= 1) {
        if (tid < s) red[tid] += red[tid + s];
        __syncthreads();
    }
    if (tid == 0) g_partials[cta] = red[0];
    if (tid < Kc) g_hist[cta * Kc + tid] = chist[tid];

    __syncthreads();
    __threadfence();
    if (tid == 0) tick[0] = atomicAdd(&g_done, 1);
    __syncthreads();

    // ================= last CTA: loss + perplexity =================
    if (tick[0] == ncta - 1) {
        __threadfence();
        float term = 0.f;
        if (tid < Kc) {
            int cnt = 0;
            for (int b = 0; b < ncta; b++) cnt += g_hist[b * Kc + tid];
            float p = (float)cnt / (float)NTOK;
            term = p * logf(p + 1e-10f);
        }
        red[tid] = term;
        __syncthreads();
        #pragma unroll
        for (int s = NTHR / 2; s > 0; s >>= 1) {
            if (tid < s) red[tid] += red[tid + s];
            __syncthreads();
        }
        float perp = expf(-red[0]);
        __syncthreads();

        red[tid] = (tid < ncta) ? g_partials[tid] : 0.f;
        __syncthreads();
        #pragma unroll
        for (int s = NTHR / 2; s > 0; s >>= 1) {
            if (tid < s) red[tid] += red[tid + s];
            __syncthreads();
        }
        if (tid == 0) {
            out[0]        = 0.25f * red[0] / ((float)NTOK * (float)Dm);
            out[OFF_PERP] = perp;
            g_done = 0;                     // reset for next graph replay
        }
    }
}

// ---------------- launch ----------------
extern "C" void kernel_launch(void* const* d_in, const int* in_sizes, int n_in,
                              void* d_out, int out_size) {
    const float* inp = (const float*)d_in[0];   // [64,2048,256] f32
    const float* emb = (const float*)d_in[1];   // [128,256]     f32
    float* out = (float*)d_out;

    int nsm = 0;
    cudaDeviceGetAttribute(&nsm, cudaDevAttrMultiProcessorCount, 0);
    if (nsm <= 0) nsm = 148;
    if (nsm > MAXCTA) nsm = MAXCTA;
    if (nsm > NTILES) nsm = NTILES;

    cudaFuncSetAttribute(vq_kernel,
                         cudaFuncAttributeMaxDynamicSharedMemorySize, SMEM_BYTES);

    vq_kernel<<<nsm, NTHR, SMEM_BYTES>>>(inp, emb, out, nsm);
}

// round 16
// speedup vs baseline: 1.7175x; 1.2212x over previous
#include <cuda_runtime.h>
#include <math.h>

#define Dm     256
#define Kc     128
#define NTOK   131072
#define TM     128                 // tokens per tile (champion geometry)
#define DC     32                  // D-chunk per smem stage
#define NTILES (NTOK / TM)         // 1024
#define NTHR   256
#define MAXCTA 256

// output layout (float32, tuple order flattened+concatenated)
#define OFF_Q    ((size_t)1)
#define OFF_PERP ((size_t)1 + (size_t)NTOK * Dm)
#define OFF_ENC  (OFF_PERP + 1)
#define OFF_IDX  (OFF_ENC + (size_t)NTOK * Kc)

__device__ int   g_hist[MAXCTA * Kc];
__device__ float g_partials[MAXCTA];
__device__ int   g_done = 0;

union F2 { float2 f; unsigned long long u; };

__device__ __forceinline__ void fma2(unsigned long long& c, unsigned long long a, unsigned long long b) {
    asm("fma.rn.f32x2 %0, %1, %2, %0;" : "+l"(c) : "l"(a), "l"(b));
}

// smem floats: As 2*32*128=8192 (32KB, XOR-swizzled), Bs 256*128=32768 (128KB, swizzled),
//              e2s 128, red 256, sidx int 128, chist int 128, tick int 4
#define SMEM_FLOATS (8192 + 32768 + 128 + 256 + 128 + 128 + 4)
#define SMEM_BYTES  (SMEM_FLOATS * 4)    // 166,424 B

extern __shared__ float smem[];

__global__ void __launch_bounds__(NTHR, 1) vq_kernel(
    const float* __restrict__ inp,
    const float* __restrict__ emb,
    float* __restrict__ out,
    int ncta)
{
    float* As    = smem;                     // [2][32][128] swizzled
    float* Bs    = smem + 8192;              // [256][128] code-swizzled
    float* e2s   = Bs + Dm * Kc;             // [128]
    float* red   = e2s + Kc;                 // [256]
    int*   sidx  = (int*)(red + NTHR);       // [128]
    int*   chist = sidx + TM;                // [128]
    int*   tick  = chist + Kc;

    const int tid = threadIdx.x;
    const int tx  = tid & 15;          // code group: codes 4tx..4tx+3, 64+4tx..+3
    const int ty  = tid >> 4;          // token group: tokens 8ty..8ty+7  (0..15)
    const int lf4 = tid & 7;           // staging: d-slot (swizzle key)
    const int lt  = tid >> 3;          // staging: token lane 0..31
    const int cta = blockIdx.x;

    if (tid < Kc) chist[tid] = 0;

    // ---- stage B swizzled: word(d,c) = d*Kc + (((c>>2)^((d>>2)&31))<<2)+(c&3) ----
    for (int i = tid; i < Kc * (Dm / 4); i += NTHR) {   // 32 iters
        int code = i >> 6;
        int f4   = i & 63;
        float4 v = *(const float4*)(emb + code * Dm + f4 * 4);
        int slot = (code >> 2) ^ (f4 & 31);
        float* p = Bs + (f4 * 4) * Kc + (slot << 2) + (code & 3);
        p[0]      = v.x;
        p[Kc]     = v.y;
        p[2 * Kc] = v.z;
        p[3 * Kc] = v.w;
    }
    __syncthreads();

    // ---- ||e_k||^2 from swizzled Bs (2 threads per code) ----
    {
        int code = tid >> 1, half = tid & 1;
        int c2 = code >> 2, cl = code & 3;
        float s = 0.f;
        #pragma unroll 8
        for (int i = 0; i < 128; i++) {
            int d = half * 128 + i;
            int slot = c2 ^ ((d >> 2) & 31);
            float v = Bs[d * Kc + (slot << 2) + cl];
            s = fmaf(v, v, s);
        }
        s += __shfl_xor_sync(0xffffffffu, s, 1);
        if (half == 0) e2s[code] = s;
    }
    __syncthreads();

    float lsum = 0.f;

    // ================= persistent tile loop =================
    for (int tile = cta; tile < NTILES; tile += ncta) {
        const int tb = tile * TM;
        float4 r[4];

        // ---- stage chunk 0: coalesced LDG + conflict-free swizzled STS + x^2 ----
        #pragma unroll
        for (int q = 0; q < 4; q++)
            r[q] = *(const float4*)(inp + (size_t)(tb + lt + 32 * q) * Dm + lf4 * 4);
        #pragma unroll
        for (int q = 0; q < 4; q++) {
            int tok = lt + 32 * q;
            int g = (tok >> 2) ^ lf4;                  // addr mod 32 = 4*lf4+lt: conflict-free
            float* p = As + (lf4 * 4) * 128 + 4 * g + (tok & 3);
            p[0]   = r[q].x;
            p[128] = r[q].y;
            p[256] = r[q].z;
            p[384] = r[q].w;
            float s = r[q].x * r[q].x;
            s = fmaf(r[q].y, r[q].y, s);
            s = fmaf(r[q].z, r[q].z, s);
            lsum += fmaf(r[q].w, r[q].w, s);           // Sum x^2 (each element once)
        }
        __syncthreads();

        // ---- accumulators: 4 token-pairs (8 tokens) x 8 codes (champion tile) ----
        unsigned long long acc[4][8];
        #pragma unroll
        for (int p = 0; p < 4; p++)
            #pragma unroll
            for (int cc = 0; cc < 8; cc++) acc[p][cc] = 0ull;

        #pragma unroll 1
        for (int c = 0; c < Dm / DC; c++) {
            if (c < Dm / DC - 1) {
                #pragma unroll
                for (int q = 0; q < 4; q++)
                    r[q] = *(const float4*)(inp + (size_t)(tb + lt + 32 * q) * Dm
                                            + (c + 1) * DC + lf4 * 4);
            }
            const float* Ac = As + (c & 1) * 4096;
            #pragma unroll 4
            for (int k = 0; k < DC; k++) {
                int kk = k >> 2;
                const float* ar = Ac + k * 128;
                float4 a0 = *(const float4*)(ar + 4 * ((2 * ty)     ^ kk));
                float4 a1 = *(const float4*)(ar + 4 * ((2 * ty + 1) ^ kk));
                int d  = c * DC + k;
                int sl = (tx ^ ((d >> 2) & 31)) << 2;
                float4 b0 = *(const float4*)(Bs + d * Kc + sl);
                float4 b1 = *(const float4*)(Bs + d * Kc + (sl ^ 64));
                F2 av[4];
                av[0].f = make_float2(a0.x, a0.y);
                av[1].f = make_float2(a0.z, a0.w);
                av[2].f = make_float2(a1.x, a1.y);
                av[3].f = make_float2(a1.z, a1.w);
                float bb[8] = {b0.x, b0.y, b0.z, b0.w, b1.x, b1.y, b1.z, b1.w};
                #pragma unroll
                for (int cc = 0; cc < 8; cc++) {
                    F2 bd; bd.f = make_float2(bb[cc], bb[cc]);
                    #pragma unroll
                    for (int p = 0; p < 4; p++) fma2(acc[p][cc], av[p].u, bd.u);
                }
            }
            if (c < Dm / DC - 1) {
                float* An = As + ((c + 1) & 1) * 4096;
                #pragma unroll
                for (int q = 0; q < 4; q++) {
                    int tok = lt + 32 * q;
                    int g = (tok >> 2) ^ lf4;
                    float* p = An + (lf4 * 4) * 128 + 4 * g + (tok & 3);
                    p[0]   = r[q].x;
                    p[128] = r[q].y;
                    p[256] = r[q].z;
                    p[384] = r[q].w;
                    float s = r[q].x * r[q].x;
                    s = fmaf(r[q].y, r[q].y, s);
                    s = fmaf(r[q].z, r[q].z, s);
                    lsum += fmaf(r[q].w, r[q].w, s);
                }
            }
            __syncthreads();
        }

        // ---- argmin per token: score = ||e||^2 - 2 dot; loss += best ----
        float e2r[8];
        #pragma unroll
        for (int j = 0; j < 4; j++) {
            e2r[j]     = e2s[tx * 4 + j];
            e2r[4 + j] = e2s[64 + tx * 4 + j];
        }
        float bsum = 0.f;
        #pragma unroll
        for (int t = 0; t < 8; t++) {
            float best = 3.402823466e38f;
            int   bi   = 0;
            #pragma unroll
            for (int cc = 0; cc < 8; cc++) {
                F2 a; a.u = acc[t >> 1][cc];
                float dot = (t & 1) ? a.f.y : a.f.x;
                float s = fmaf(-2.0f, dot, e2r[cc]);
                int code = (cc < 4) ? (tx * 4 + cc) : (64 + tx * 4 + (cc - 4));
                if (s < best) { best = s; bi = code; }   // ascending order -> first-min
            }
            #pragma unroll
            for (int m = 1; m < 16; m <<= 1) {
                float ov = __shfl_xor_sync(0xffffffffu, best, m);
                int   oi = __shfl_xor_sync(0xffffffffu, bi,   m);
                if (ov < best || (ov == best && oi < bi)) { best = ov; bi = oi; }
            }
            if (tx == 0) { sidx[ty * 8 + t] = bi; bsum += best; }
        }
        if (tx == 0) lsum += bsum;
        __syncthreads();   // sidx ready

        // histogram
        if (tid < TM) atomicAdd(&chist[sidx[tid]], 1);

        // ---- quantized output (region starts at elem 1 -> scalar stores) ----
        float* out_q = out + OFF_Q;
        #pragma unroll 1
        for (int i = tid; i < TM * (Dm / 4); i += NTHR) {   // 32 iters
            int tok = i >> 6, f4 = i & 63;
            int k2 = sidx[tok];
            float4 e = *(const float4*)(emb + (size_t)k2 * Dm + f4 * 4);
            float* qp = out_q + (size_t)(tb + tok) * Dm + f4 * 4;
            qp[0] = e.x; qp[1] = e.y; qp[2] = e.z; qp[3] = e.w;
        }

        // ---- one-hot encodings (region start == 2 mod 4 -> float2 ok) ----
        float* out_e = out + OFF_ENC;
        #pragma unroll 1
        for (int i = tid; i < TM * (Kc / 4); i += NTHR) {   // 16 iters
            int tok = i >> 5, f4 = i & 31;
            int k2 = sidx[tok];
            int d0 = f4 * 4;
            float2 v01, v23;
            v01.x = (d0 + 0 == k2) ? 1.f : 0.f;
            v01.y = (d0 + 1 == k2) ? 1.f : 0.f;
            v23.x = (d0 + 2 == k2) ? 1.f : 0.f;
            v23.y = (d0 + 3 == k2) ? 1.f : 0.f;
            float* ep = out_e + (size_t)(tb + tok) * Kc + d0;
            *(float2*)(ep)     = v01;
            *(float2*)(ep + 2) = v23;
        }

        // indices (as float)
        if (tid < TM) out[OFF_IDX + tb + tid] = (float)sidx[tid];
        __syncthreads();   // protect sidx/As before next tile
    }

    // ================= per-CTA results =================
    red[tid] = lsum;
    __syncthreads();
    #pragma unroll
    for (int s = NTHR / 2; s > 0; s >>= 1) {
        if (tid < s) red[tid] += red[tid + s];
        __syncthreads();
    }
    if (tid == 0) g_partials[cta] = red[0];
    if (tid < Kc) g_hist[cta * Kc + tid] = chist[tid];

    __syncthreads();
    __threadfence();
    if (tid == 0) tick[0] = atomicAdd(&g_done, 1);
    __syncthreads();

    // ================= last CTA: loss + perplexity =================
    if (tick[0] == ncta - 1) {
        __threadfence();
        float term = 0.f;
        if (tid < Kc) {
            int cnt = 0;
            for (int b = 0; b < ncta; b++) cnt += g_hist[b * Kc + tid];
            float p = (float)cnt / (float)NTOK;
            term = p * logf(p + 1e-10f);
        }
        red[tid] = term;
        __syncthreads();
        #pragma unroll
        for (int s = NTHR / 2; s > 0; s >>= 1) {
            if (tid < s) red[tid] += red[tid + s];
            __syncthreads();
        }
        float perp = expf(-red[0]);
        __syncthreads();

        red[tid] = (tid < ncta) ? g_partials[tid] : 0.f;
        __syncthreads();
        #pragma unroll
        for (int s = NTHR / 2; s > 0; s >>= 1) {
            if (tid < s) red[tid] += red[tid + s];
            __syncthreads();
        }
        if (tid == 0) {
            out[0]        = 0.25f * red[0] / ((float)NTOK * (float)Dm);
            out[OFF_PERP] = perp;
            g_done = 0;                     // reset for next graph replay
        }
    }
}

// ---------------- launch ----------------
extern "C" void kernel_launch(void* const* d_in, const int* in_sizes, int n_in,
                              void* d_out, int out_size) {
    const float* inp = (const float*)d_in[0];   // [64,2048,256] f32
    const float* emb = (const float*)d_in[1];   // [128,256]     f32
    float* out = (float*)d_out;

    int nsm = 0;
    cudaDeviceGetAttribute(&nsm, cudaDevAttrMultiProcessorCount, 0);
    if (nsm <= 0) nsm = 148;
    if (nsm > MAXCTA) nsm = MAXCTA;
    if (nsm > NTILES) nsm = NTILES;

    cudaFuncSetAttribute(vq_kernel,
                         cudaFuncAttributeMaxDynamicSharedMemorySize, SMEM_BYTES);

    vq_kernel<<<nsm, NTHR, SMEM_BYTES>>>(inp, emb, out, nsm);
}